// round 5
// baseline (speedup 1.0000x reference)
#include <cuda_runtime.h>
#include <cstdint>

#define N_NODES 100000
#define N_EDGES 20000
#define NNZ     1000000
#define D       64
#define ESTRIDE 112          // max incidences per edge bin (Poisson(50), ~9 sigma)
#define VSTRIDE 40           // max incidences per vertex bin (Poisson(10), ~9 sigma)

// ---------------- scratch (device globals; allocation-free) ----------------
__device__ float g_Xsum[N_EDGES * D];       // per-edge sum of X rows
__device__ float g_Z   [N_EDGES * D];       // Xsum @ W1Bf + deg*bZ
__device__ float g_SZ  [N_NODES * D];       // per-vertex sum of Z rows
__device__ int   g_cur_e[N_EDGES];          // edge incidence count (true deg)
__device__ int   g_cur_v[N_NODES];          // vertex incidence count (true deg)
__device__ int   g_adj_e[N_EDGES * ESTRIDE];
__device__ int   g_adj_v[N_NODES * VSTRIDE];
__device__ float g_W1T [D * D];             // W1_w transposed [k][j]
__device__ float g_Bf  [D * D];             // W2b^T @ W^T
__device__ float g_W1Bf[D * D];             // W1T @ Bf
__device__ float g_bZ  [D];                 // b1 @ Bf
__device__ float g_WcatA[128 * D];          // [A | W^T] stacked, [k][j]
__device__ float g_cvec[D];                 // b2 @ W^T

// ---------------------------------------------------------------------------
// k_pre: fold weights (stage 1).
// ---------------------------------------------------------------------------
__global__ void k_pre(const float* __restrict__ W1_w,
                      const float* __restrict__ W2_w,
                      const float* __restrict__ W2_b,
                      const float* __restrict__ W_w) {
    __shared__ float WT[64 * 64];   // WT[m][j] = W_w[j][m]
    int tid = threadIdx.x;
    for (int i = tid; i < 4096; i += 256) {
        int j = i >> 6, m = i & 63;
        WT[m * 64 + j] = W_w[i];
    }
    __syncthreads();
    int idx = blockIdx.x * 256 + tid;
    if (idx < 4096) {                              // A = W2a^T @ W^T
        int k = idx >> 6, j = idx & 63;
        float acc = 0.f;
        #pragma unroll 8
        for (int m = 0; m < 64; m++) acc += W2_w[m * 128 + k] * WT[m * 64 + j];
        g_WcatA[k * 64 + j] = acc;
    } else if (idx < 8192) {                       // W^T copy
        int t = idx - 4096;
        g_WcatA[4096 + t] = WT[t];
    } else if (idx < 12288) {                      // Bf = W2b^T @ W^T
        int t = idx - 8192;
        int k = t >> 6, j = t & 63;
        float acc = 0.f;
        #pragma unroll 8
        for (int m = 0; m < 64; m++) acc += W2_w[m * 128 + 64 + k] * WT[m * 64 + j];
        g_Bf[k * 64 + j] = acc;
    } else if (idx < 16384) {                      // W1T
        int t = idx - 12288;
        int k = t >> 6, j = t & 63;
        g_W1T[k * 64 + j] = W1_w[j * 64 + k];
    } else if (idx < 16448) {                      // cvec
        int j = idx - 16384;
        float acc = 0.f;
        for (int m = 0; m < 64; m++) acc += W2_b[m] * WT[m * 64 + j];
        g_cvec[j] = acc;
    }
}

// ---------------------------------------------------------------------------
// k_pre2: stage 2 (needs Bf, W1T): W1Bf = W1T @ Bf;  bZ = b1 @ Bf
// ---------------------------------------------------------------------------
__global__ void k_pre2(const float* __restrict__ b1) {
    __shared__ float Bfs[64 * 64];
    int tid = threadIdx.x;
    for (int i = tid; i < 4096; i += 256) Bfs[i] = g_Bf[i];
    __syncthreads();
    int idx = blockIdx.x * 256 + tid;
    if (idx < 4096) {
        int k = idx >> 6, j = idx & 63;
        float acc = 0.f;
        #pragma unroll 8
        for (int m = 0; m < 64; m++) acc += g_W1T[k * 64 + m] * Bfs[m * 64 + j];
        g_W1Bf[k * 64 + j] = acc;
    } else if (idx < 4160) {
        int j = idx - 4096;
        float acc = 0.f;
        for (int m = 0; m < 64; m++) acc += b1[m] * Bfs[m * 64 + j];
        g_bZ[j] = acc;
    }
}

// ---------------------------------------------------------------------------
// k_fill: fixed-stride binning, 2 incidences per thread.
// ---------------------------------------------------------------------------
__global__ __launch_bounds__(256) void k_fill(const int* __restrict__ vertex,
                                              const int* __restrict__ edges) {
    int i = blockIdx.x * 256 + threadIdx.x;
    if (i * 2 >= NNZ) return;
    int2 v2 = __ldg((const int2*)vertex + i);
    int2 e2 = __ldg((const int2*)edges + i);
    int se0 = atomicAdd(&g_cur_e[e2.x], 1);
    if (se0 < ESTRIDE) g_adj_e[e2.x * ESTRIDE + se0] = v2.x;
    int sv0 = atomicAdd(&g_cur_v[v2.x], 1);
    if (sv0 < VSTRIDE) g_adj_v[v2.x * VSTRIDE + sv0] = e2.x;
    int se1 = atomicAdd(&g_cur_e[e2.y], 1);
    if (se1 < ESTRIDE) g_adj_e[e2.y * ESTRIDE + se1] = v2.y;
    int sv1 = atomicAdd(&g_cur_v[v2.y], 1);
    if (sv1 < VSTRIDE) g_adj_v[v2.y * VSTRIDE + sv1] = e2.y;
}

// ---------------------------------------------------------------------------
// k_gather_e: Xsum[e] = sum over adj_e[e] of X[v]. Half-warp per edge.
// ---------------------------------------------------------------------------
__global__ __launch_bounds__(256) void k_gather_e(const float* __restrict__ X) {
    int t = threadIdx.x;
    int seg = blockIdx.x * 16 + (t >> 4);
    if (seg >= N_EDGES) return;
    int lane = t & 15;
    int d = g_cur_e[seg];
    if (d > ESTRIDE) d = ESTRIDE;
    const int* adj = g_adj_e + seg * ESTRIDE;
    const float4* X4 = (const float4*)X;
    float4 acc = make_float4(0.f, 0.f, 0.f, 0.f);
    int j = 0;
    for (; j + 4 <= d; j += 4) {
        int a0 = __ldg(adj + j + 0);
        int a1 = __ldg(adj + j + 1);
        int a2 = __ldg(adj + j + 2);
        int a3 = __ldg(adj + j + 3);
        float4 x0 = X4[(size_t)a0 * 16 + lane];
        float4 x1 = X4[(size_t)a1 * 16 + lane];
        float4 x2 = X4[(size_t)a2 * 16 + lane];
        float4 x3 = X4[(size_t)a3 * 16 + lane];
        acc.x += (x0.x + x1.x) + (x2.x + x3.x);
        acc.y += (x0.y + x1.y) + (x2.y + x3.y);
        acc.z += (x0.z + x1.z) + (x2.z + x3.z);
        acc.w += (x0.w + x1.w) + (x2.w + x3.w);
    }
    for (; j < d; j++) {
        int a0 = __ldg(adj + j);
        float4 x0 = X4[(size_t)a0 * 16 + lane];
        acc.x += x0.x; acc.y += x0.y; acc.z += x0.z; acc.w += x0.w;
    }
    ((float4*)g_Xsum)[(size_t)seg * 16 + lane] = acc;
}

// ---------------------------------------------------------------------------
// k_gather_v: SZ[v] = sum over adj_v[v] of Z[e]. Half-warp per vertex.
// ---------------------------------------------------------------------------
__global__ __launch_bounds__(256) void k_gather_v() {
    int t = threadIdx.x;
    int seg = blockIdx.x * 16 + (t >> 4);
    if (seg >= N_NODES) return;
    int lane = t & 15;
    int d = g_cur_v[seg];
    if (d > VSTRIDE) d = VSTRIDE;
    const int* adj = g_adj_v + seg * VSTRIDE;
    const float4* Z4 = (const float4*)g_Z;
    float4 acc = make_float4(0.f, 0.f, 0.f, 0.f);
    int j = 0;
    for (; j + 4 <= d; j += 4) {
        int a0 = __ldg(adj + j + 0);
        int a1 = __ldg(adj + j + 1);
        int a2 = __ldg(adj + j + 2);
        int a3 = __ldg(adj + j + 3);
        float4 x0 = Z4[(size_t)a0 * 16 + lane];
        float4 x1 = Z4[(size_t)a1 * 16 + lane];
        float4 x2 = Z4[(size_t)a2 * 16 + lane];
        float4 x3 = Z4[(size_t)a3 * 16 + lane];
        acc.x += (x0.x + x1.x) + (x2.x + x3.x);
        acc.y += (x0.y + x1.y) + (x2.y + x3.y);
        acc.z += (x0.z + x1.z) + (x2.z + x3.z);
        acc.w += (x0.w + x1.w) + (x2.w + x3.w);
    }
    for (; j < d; j++) {
        int a0 = __ldg(adj + j);
        float4 x0 = Z4[(size_t)a0 * 16 + lane];
        acc.x += x0.x; acc.y += x0.y; acc.z += x0.z; acc.w += x0.w;
    }
    ((float4*)g_SZ)[(size_t)seg * 16 + lane] = acc;
}

// ---------------------------------------------------------------------------
// k_edge_gemm: two INDEPENDENT GEMMs from one tile:
//   Xe = Xsum @ W1T  + deg_e*b1  -> XeOut (d_out)
//   Z  = Xsum @ W1Bf + deg_e*bZ  -> g_Z
// 32-row tiles (grid 625), 256 threads, 2 rows x 4 cols x 2 outputs/thread.
// ---------------------------------------------------------------------------
__global__ __launch_bounds__(256) void k_edge_gemm(const float* __restrict__ b1,
                                                   float* __restrict__ XeOut) {
    __shared__ float Xs[64][34];    // [k][r]
    __shared__ float W1s[64][64];
    __shared__ float W2s[64][64];
    __shared__ float bs[64], bzs[64], degs[32];
    int tid = threadIdx.x;
    int row0 = blockIdx.x * 32;

    for (int i = tid; i < 1024; i += 256) {
        ((float4*)W1s)[i] = ((const float4*)g_W1T)[i];
        ((float4*)W2s)[i] = ((const float4*)g_W1Bf)[i];
    }
    if (tid < 64) {
        bs[tid] = b1[tid];
        bzs[tid] = g_bZ[tid];
    } else if (tid < 96) {
        int r = row0 + tid - 64;
        degs[tid - 64] = (r < N_EDGES) ? (float)g_cur_e[r] : 0.f;
    }
    #pragma unroll
    for (int i = 0; i < 2; i++) {
        int f = tid + i * 256;
        int r = f >> 4, k4 = f & 15;
        int row = row0 + r;
        float4 x = (row < N_EDGES) ? ((const float4*)g_Xsum)[row * 16 + k4]
                                   : make_float4(0.f, 0.f, 0.f, 0.f);
        Xs[k4 * 4 + 0][r] = x.x; Xs[k4 * 4 + 1][r] = x.y;
        Xs[k4 * 4 + 2][r] = x.z; Xs[k4 * 4 + 3][r] = x.w;
    }
    __syncthreads();

    int tx = tid & 15, ty = tid >> 4;   // 16 x 16
    int tx4 = tx * 4, ty2 = ty * 2;
    float a1[2][4] = {}, a2[2][4] = {};
    #pragma unroll 16
    for (int k = 0; k < 64; k++) {
        float2 a = *(const float2*)&Xs[k][ty2];
        float4 w1 = *(const float4*)&W1s[k][tx4];
        float4 w2 = *(const float4*)&W2s[k][tx4];
        a1[0][0] += a.x * w1.x; a1[0][1] += a.x * w1.y;
        a1[0][2] += a.x * w1.z; a1[0][3] += a.x * w1.w;
        a1[1][0] += a.y * w1.x; a1[1][1] += a.y * w1.y;
        a1[1][2] += a.y * w1.z; a1[1][3] += a.y * w1.w;
        a2[0][0] += a.x * w2.x; a2[0][1] += a.x * w2.y;
        a2[0][2] += a.x * w2.z; a2[0][3] += a.x * w2.w;
        a2[1][0] += a.y * w2.x; a2[1][1] += a.y * w2.y;
        a2[1][2] += a.y * w2.z; a2[1][3] += a.y * w2.w;
    }
    #pragma unroll
    for (int r = 0; r < 2; r++) {
        int row = row0 + ty2 + r;
        if (row < N_EDGES) {
            float dg = degs[ty2 + r];
            float4 xe = make_float4(a1[r][0] + dg * bs[tx4 + 0],
                                    a1[r][1] + dg * bs[tx4 + 1],
                                    a1[r][2] + dg * bs[tx4 + 2],
                                    a1[r][3] + dg * bs[tx4 + 3]);
            float4 z  = make_float4(a2[r][0] + dg * bzs[tx4 + 0],
                                    a2[r][1] + dg * bzs[tx4 + 1],
                                    a2[r][2] + dg * bzs[tx4 + 2],
                                    a2[r][3] + dg * bzs[tx4 + 3]);
            ((float4*)XeOut)[(size_t)row * 16 + tx] = xe;
            ((float4*)g_Z)[(size_t)row * 16 + tx]   = z;
        }
    }
}

// ---------------------------------------------------------------------------
// k_node_out (f32x2 packed FMA):
// out = 0.5*deg*(X@A) + 0.5*(X0@W^T) + 0.5*SZ + 0.5*deg*cvec + Wb
// ---------------------------------------------------------------------------
#define FMA_X2(d, a, b) \
    asm("fma.rn.f32x2 %0, %1, %2, %0;" : "+l"(d) : "l"(a), "l"(b))

#define XS_STRIDE 132   // floats per k-row; multiple of 4 -> 16B alignment kept

__global__ __launch_bounds__(256) void k_node_out(const float* __restrict__ X,
                                                  const float* __restrict__ X0,
                                                  const float* __restrict__ Wb,
                                                  float* __restrict__ out) {
    extern __shared__ char sm_raw[];
    float* Xs = (float*)sm_raw;                                        // [64][132]
    unsigned long long* Wd =
        (unsigned long long*)(sm_raw + 64 * XS_STRIDE * 4);            // [64][64] dup pairs
    float* degs = (float*)(sm_raw + 64 * XS_STRIDE * 4 + 64 * 64 * 8); // [128] = 0.5*deg
    float* cv   = degs + 128;                                          // [64]
    float* bb   = cv + 64;                                             // [64]

    int tid = threadIdx.x;
    int row0 = blockIdx.x * 128;

    if (tid < 128) {
        int r = row0 + tid;
        degs[tid] = (r < N_NODES) ? 0.5f * (float)g_cur_v[r] : 0.f;
    } else if (tid < 192) {
        cv[tid - 128] = g_cvec[tid - 128];
    } else {
        bb[tid - 192] = Wb[tid - 192];
    }
    __syncthreads();

    int tx = tid & 15, ty = tid >> 4;
    int tx4 = tx * 4, ty8 = ty * 8;

    unsigned long long acc[4][4];
    #pragma unroll
    for (int p = 0; p < 4; p++)
        #pragma unroll
        for (int c = 0; c < 4; c++) acc[p][c] = 0ULL;

    #pragma unroll
    for (int kb = 0; kb < 2; kb++) {
        const float* src = (kb == 0) ? X : X0;
        #pragma unroll
        for (int i = 0; i < 8; i++) {
            int f = tid + i * 256;
            int r = f >> 4, k4 = f & 15;
            int row = row0 + r;
            float s = (kb == 0) ? degs[r] : 0.5f;
            float4 x = (row < N_NODES) ? ((const float4*)src)[row * 16 + k4]
                                       : make_float4(0.f, 0.f, 0.f, 0.f);
            Xs[(k4 * 4 + 0) * XS_STRIDE + r] = s * x.x;
            Xs[(k4 * 4 + 1) * XS_STRIDE + r] = s * x.y;
            Xs[(k4 * 4 + 2) * XS_STRIDE + r] = s * x.z;
            Xs[(k4 * 4 + 3) * XS_STRIDE + r] = s * x.w;
        }
        for (int i = tid; i < 4096; i += 256) {
            float w = g_WcatA[kb * 4096 + i];
            ((float2*)Wd)[i] = make_float2(w, w);
        }
        __syncthreads();

        #pragma unroll 8
        for (int k = 0; k < 64; k++) {
            ulonglong2 a01 = *(const ulonglong2*)(Xs + k * XS_STRIDE + ty8);
            ulonglong2 a23 = *(const ulonglong2*)(Xs + k * XS_STRIDE + ty8 + 4);
            ulonglong2 b01 = *(const ulonglong2*)(Wd + k * 64 + tx4);
            ulonglong2 b23 = *(const ulonglong2*)(Wd + k * 64 + tx4 + 2);
            FMA_X2(acc[0][0], a01.x, b01.x); FMA_X2(acc[0][1], a01.x, b01.y);
            FMA_X2(acc[0][2], a01.x, b23.x); FMA_X2(acc[0][3], a01.x, b23.y);
            FMA_X2(acc[1][0], a01.y, b01.x); FMA_X2(acc[1][1], a01.y, b01.y);
            FMA_X2(acc[1][2], a01.y, b23.x); FMA_X2(acc[1][3], a01.y, b23.y);
            FMA_X2(acc[2][0], a23.x, b01.x); FMA_X2(acc[2][1], a23.x, b01.y);
            FMA_X2(acc[2][2], a23.x, b23.x); FMA_X2(acc[2][3], a23.x, b23.y);
            FMA_X2(acc[3][0], a23.y, b01.x); FMA_X2(acc[3][1], a23.y, b01.y);
            FMA_X2(acc[3][2], a23.y, b23.x); FMA_X2(acc[3][3], a23.y, b23.y);
        }
        __syncthreads();
    }

    const float4* SZ4 = (const float4*)g_SZ;
    #pragma unroll
    for (int p = 0; p < 4; p++) {
        float lo[4], hi[4];
        #pragma unroll
        for (int c = 0; c < 4; c++) {
            asm("mov.b64 {%0, %1}, %2;" : "=f"(lo[c]), "=f"(hi[c]) : "l"(acc[p][c]));
        }
        int rl = ty8 + 2 * p;
        int row_lo = row0 + rl;
        int row_hi = row_lo + 1;
        if (row_lo < N_NODES) {
            float hd = degs[rl];
            float4 sz = SZ4[(size_t)row_lo * 16 + tx];
            float4 o;
            o.x = lo[0] + 0.5f * sz.x + hd * cv[tx4 + 0] + bb[tx4 + 0];
            o.y = lo[1] + 0.5f * sz.y + hd * cv[tx4 + 1] + bb[tx4 + 1];
            o.z = lo[2] + 0.5f * sz.z + hd * cv[tx4 + 2] + bb[tx4 + 2];
            o.w = lo[3] + 0.5f * sz.w + hd * cv[tx4 + 3] + bb[tx4 + 3];
            ((float4*)out)[(size_t)row_lo * 16 + tx] = o;
        }
        if (row_hi < N_NODES) {
            float hd = degs[rl + 1];
            float4 sz = SZ4[(size_t)row_hi * 16 + tx];
            float4 o;
            o.x = hi[0] + 0.5f * sz.x + hd * cv[tx4 + 0] + bb[tx4 + 0];
            o.y = hi[1] + 0.5f * sz.y + hd * cv[tx4 + 1] + bb[tx4 + 1];
            o.z = hi[2] + 0.5f * sz.z + hd * cv[tx4 + 2] + bb[tx4 + 2];
            o.w = hi[3] + 0.5f * sz.w + hd * cv[tx4 + 3] + bb[tx4 + 3];
            ((float4*)out)[(size_t)row_hi * 16 + tx] = o;
        }
    }
}

#define NODE_SMEM (64 * XS_STRIDE * 4 + 64 * 64 * 8 + 128 * 4 + 64 * 4 + 64 * 4)

// ---------------------------------------------------------------------------
extern "C" void kernel_launch(void* const* d_in, const int* in_sizes, int n_in,
                              void* d_out, int out_size) {
    const float* X      = (const float*)d_in[0];
    const float* X0     = (const float*)d_in[1];
    const int*   vertex = (const int*)d_in[2];
    const int*   edges  = (const int*)d_in[3];
    const float* W1_w   = (const float*)d_in[4];
    const float* W1_b   = (const float*)d_in[5];
    const float* W2_w   = (const float*)d_in[6];
    const float* W2_b   = (const float*)d_in[7];
    const float* W_w    = (const float*)d_in[8];
    const float* W_b    = (const float*)d_in[9];

    float* out   = (float*)d_out;                       // [N_NODES, 64]
    float* XeOut = (float*)d_out + (size_t)N_NODES * D; // [N_EDGES, 64]

    static_assert(NODE_SMEM < 100 * 1024, "smem");
    cudaFuncSetAttribute(k_node_out, cudaFuncAttributeMaxDynamicSharedMemorySize,
                         NODE_SMEM);

    void *cureP = nullptr, *curvP = nullptr;
    cudaGetSymbolAddress(&cureP, g_cur_e);
    cudaGetSymbolAddress(&curvP, g_cur_v);
    cudaMemsetAsync(cureP, 0, (size_t)N_EDGES * sizeof(int), 0);
    cudaMemsetAsync(curvP, 0, (size_t)N_NODES * sizeof(int), 0);

    k_pre<<<65, 256>>>(W1_w, W2_w, W2_b, W_w);
    k_pre2<<<17, 256>>>(W1_b);

    k_fill<<<(NNZ / 2 + 255) / 256, 256>>>(vertex, edges);

    k_gather_e<<<(N_EDGES + 15) / 16, 256>>>(X);
    k_edge_gemm<<<(N_EDGES + 31) / 32, 256>>>(W1_b, XeOut);
    k_gather_v<<<(N_NODES + 15) / 16, 256>>>();
    k_node_out<<<(N_NODES + 127) / 128, 256, NODE_SMEM>>>(X, X0, W_b, out);
}